// round 3
// baseline (speedup 1.0000x reference)
#include <cuda_runtime.h>
#include <cstdint>

// out[s,b,d] = x[s,b,d] + ((S-1)*0.5f - s)
// Pure HBM stream, 268 MB total. 256-bit vector loads/stores (sm_103a
// LDG.E.256 / STG.E.256) with evict-first (.cs) policy: zero reuse.
//
// Each v8 index covers 8 contiguous floats. Floats per s = B*D = 8192,
// so v8-chunks per s = 1024  ->  s = i >> 10.

__global__ void __launch_bounds__(256)
relpos_add_kernel(const float* __restrict__ x,
                  float* __restrict__ out,
                  int n8, float half_sm1) {
    int i = blockIdx.x * blockDim.x + threadIdx.x;
    if (i >= n8) return;

    float bias = half_sm1 - (float)(i >> 10);

    const float* px = x + (size_t)i * 8;
    float* po = out + (size_t)i * 8;

    float a0, a1, a2, a3, a4, a5, a6, a7;
    asm volatile(
        "ld.global.cs.v8.f32 {%0,%1,%2,%3,%4,%5,%6,%7}, [%8];"
        : "=f"(a0), "=f"(a1), "=f"(a2), "=f"(a3),
          "=f"(a4), "=f"(a5), "=f"(a6), "=f"(a7)
        : "l"(px));

    a0 += bias; a1 += bias; a2 += bias; a3 += bias;
    a4 += bias; a5 += bias; a6 += bias; a7 += bias;

    asm volatile(
        "st.global.cs.v8.f32 [%0], {%1,%2,%3,%4,%5,%6,%7,%8};"
        :
        : "l"(po),
          "f"(a0), "f"(a1), "f"(a2), "f"(a3),
          "f"(a4), "f"(a5), "f"(a6), "f"(a7)
        : "memory");
}

extern "C" void kernel_launch(void* const* d_in, const int* in_sizes, int n_in,
                              void* d_out, int out_size) {
    const float* x = (const float*)d_in[0];
    float* out = (float*)d_out;

    const int total = in_sizes[0];        // 33,554,432
    const int n8 = total / 8;             // 4,194,304
    const int seq_len = total / 8192;     // 4096
    const float half_sm1 = 0.5f * (float)(seq_len - 1);

    const int threads = 256;
    const int blocks = (n8 + threads - 1) / threads;   // 16384
    relpos_add_kernel<<<blocks, threads>>>(x, out, n8, half_sm1);
}

// round 4
// speedup vs baseline: 1.0147x; 1.0147x over previous
#include <cuda_runtime.h>
#include <cstdint>

// out[s,b,d] = x[s,b,d] + ((S-1)*0.5f - s)
// Pure HBM stream, 268 MB total — at the measured mixed-stream HBM ceiling
// (~6.0 TB/s). 256-bit vector ld/st (.cs, zero reuse), 2 independent v8
// chunks per thread (MLP=2 front-batched), block=512, grid=4096.
//
// Each v8 chunk covers 8 contiguous floats; floats per s = B*D = 8192,
// so v8-chunks per s = 1024  ->  s = chunk_idx >> 10.

__global__ void __launch_bounds__(512)
relpos_add_kernel(const float* __restrict__ x,
                  float* __restrict__ out,
                  int n8, float half_sm1) {
    int i0 = (blockIdx.x * blockDim.x) * 2 + threadIdx.x;
    int i1 = i0 + blockDim.x;

    float a0, a1, a2, a3, a4, a5, a6, a7;
    float b0, b1, b2, b3, b4, b5, b6, b7;

    bool p0 = (i0 < n8);
    bool p1 = (i1 < n8);

    const float* px0 = x + (size_t)i0 * 8;
    const float* px1 = x + (size_t)i1 * 8;

    // Front-batched independent 256-bit loads (MLP=2)
    if (p0)
        asm volatile("ld.global.cs.v8.f32 {%0,%1,%2,%3,%4,%5,%6,%7}, [%8];"
                     : "=f"(a0), "=f"(a1), "=f"(a2), "=f"(a3),
                       "=f"(a4), "=f"(a5), "=f"(a6), "=f"(a7)
                     : "l"(px0));
    if (p1)
        asm volatile("ld.global.cs.v8.f32 {%0,%1,%2,%3,%4,%5,%6,%7}, [%8];"
                     : "=f"(b0), "=f"(b1), "=f"(b2), "=f"(b3),
                       "=f"(b4), "=f"(b5), "=f"(b6), "=f"(b7)
                     : "l"(px1));

    if (p0) {
        float bias = half_sm1 - (float)(i0 >> 10);
        a0 += bias; a1 += bias; a2 += bias; a3 += bias;
        a4 += bias; a5 += bias; a6 += bias; a7 += bias;
        float* po = out + (size_t)i0 * 8;
        asm volatile("st.global.cs.v8.f32 [%0], {%1,%2,%3,%4,%5,%6,%7,%8};"
                     :
                     : "l"(po),
                       "f"(a0), "f"(a1), "f"(a2), "f"(a3),
                       "f"(a4), "f"(a5), "f"(a6), "f"(a7)
                     : "memory");
    }
    if (p1) {
        float bias = half_sm1 - (float)(i1 >> 10);
        b0 += bias; b1 += bias; b2 += bias; b3 += bias;
        b4 += bias; b5 += bias; b6 += bias; b7 += bias;
        float* po = out + (size_t)i1 * 8;
        asm volatile("st.global.cs.v8.f32 [%0], {%1,%2,%3,%4,%5,%6,%7,%8};"
                     :
                     : "l"(po),
                       "f"(b0), "f"(b1), "f"(b2), "f"(b3),
                       "f"(b4), "f"(b5), "f"(b6), "f"(b7)
                     : "memory");
    }
}

extern "C" void kernel_launch(void* const* d_in, const int* in_sizes, int n_in,
                              void* d_out, int out_size) {
    const float* x = (const float*)d_in[0];
    float* out = (float*)d_out;

    const int total = in_sizes[0];        // 33,554,432
    const int n8 = total / 8;             // 4,194,304
    const int seq_len = total / 8192;     // 4096
    const float half_sm1 = 0.5f * (float)(seq_len - 1);

    const int threads = 512;
    const int per_block = threads * 2;
    const int blocks = (n8 + per_block - 1) / per_block;  // 4096
    relpos_add_kernel<<<blocks, threads>>>(x, out, n8, half_sm1);
}